// round 2
// baseline (speedup 1.0000x reference)
#include <cuda_runtime.h>
#include <cuda_bf16.h>

// Problem constants
#define NB   64
#define CI   128
#define CO   128
#define HH   56
#define WW   56
#define XN   (NB*CI*HH*WW)      // 25,690,112
#define WN   (CO*CI*3*3)        // 147,456
#define XGROUPS (XN/16)         // 1,605,632
#define WGROUPS (WN/16)         // 9,216

// Scratch: quantized operands (exact BFP values in fp32).
__device__ float g_xq[XN];
__device__ float g_wq[WN];

// ---------------------------------------------------------------------------
// BFP quantization: groups of 16 consecutive (flattened) elements share the
// exponent of the max-abs element. q = clip(rint(v * 2^(7-e)), -127, 127) * 2^(e-7)
// rintf == round-half-to-even == jnp.round. Scales are exact powers of two.
// ---------------------------------------------------------------------------
__device__ __forceinline__ void quant_group(const float* __restrict__ in,
                                            float* __restrict__ out, int g) {
    const float4* p = reinterpret_cast<const float4*>(in) + (size_t)g * 4;
    float v[16];
    float4 a = p[0], b = p[1], c = p[2], d = p[3];
    v[0]=a.x;  v[1]=a.y;  v[2]=a.z;  v[3]=a.w;
    v[4]=b.x;  v[5]=b.y;  v[6]=b.z;  v[7]=b.w;
    v[8]=c.x;  v[9]=c.y;  v[10]=c.z; v[11]=c.w;
    v[12]=d.x; v[13]=d.y; v[14]=d.z; v[15]=d.w;

    float m = 0.0f;
    #pragma unroll
    for (int i = 0; i < 16; i++) m = fmaxf(m, fabsf(v[i]));

    float ov[16];
    if (m > 0.0f) {
        int e = ((__float_as_int(m) >> 23) & 0xFF) - 127;   // floor(log2(m)), m normal
        float inv_s = ldexpf(1.0f, 7 - e);                  // exact 2^(7-e)
        float s     = ldexpf(1.0f, e - 7);                  // exact 2^(e-7)
        #pragma unroll
        for (int i = 0; i < 16; i++) {
            float q = rintf(v[i] * inv_s);
            q = fminf(127.0f, fmaxf(-127.0f, q));
            ov[i] = q * s;
        }
    } else {
        #pragma unroll
        for (int i = 0; i < 16; i++) ov[i] = 0.0f;
    }
    float4* po = reinterpret_cast<float4*>(out) + (size_t)g * 4;
    po[0] = make_float4(ov[0],  ov[1],  ov[2],  ov[3]);
    po[1] = make_float4(ov[4],  ov[5],  ov[6],  ov[7]);
    po[2] = make_float4(ov[8],  ov[9],  ov[10], ov[11]);
    po[3] = make_float4(ov[12], ov[13], ov[14], ov[15]);
}

__global__ void quant_x_kernel(const float* __restrict__ in) {
    int g = blockIdx.x * blockDim.x + threadIdx.x;
    if (g < XGROUPS) quant_group(in, g_xq, g);
}

__global__ void quant_w_kernel(const float* __restrict__ in) {
    int g = blockIdx.x * blockDim.x + threadIdx.x;
    if (g < WGROUPS) quant_group(in, g_wq, g);
}

// ---------------------------------------------------------------------------
// Direct 3x3 conv, stride 1, pad 1, NCHW, fp32 accumulate.
// Block tile: one image n, 64 output channels, 4 output rows, all 56 cols.
// Threads: 224 = 8 co-groups (8 couts each) x 28 pixel-groups (4h x 7 groups of 8w).
// ci staged in chunks of 8 through shared memory (with spatial halo).
// Per inner (ci,kh,kw): 8 x-loads + 8 w-loads -> 64 FFMA (register blocked).
// ---------------------------------------------------------------------------
#define CI_T 8
#define CO_T 64
#define H_T  4
#define NTHR 224

__global__ __launch_bounds__(NTHR, 2)
void conv_kernel(float* __restrict__ out) {
    __shared__ float xs[CI_T][H_T + 2][WW + 2];   // 8 x 6 x 58
    __shared__ float ws[CO_T][CI_T * 9];          // 64 x 72

    const int t   = threadIdx.x;
    const int hb  = blockIdx.x;        // 0..13
    const int cb  = blockIdx.y;        // 0..1
    const int n   = blockIdx.z;        // 0..63
    const int h0  = hb * H_T;
    const int co0 = cb * CO_T;

    const int co_g = t / 28;           // 0..7
    const int pix  = t % 28;
    const int ph   = pix / 7;          // 0..3
    const int pw   = (pix % 7) * 8;    // 0,8,...,48

    float acc[8][8];
    #pragma unroll
    for (int c = 0; c < 8; c++)
        #pragma unroll
        for (int j = 0; j < 8; j++) acc[c][j] = 0.0f;

    const float* xbase = g_xq + (size_t)n * CI * HH * WW;

    for (int cc = 0; cc < CI / CI_T; cc++) {
        // Stage x chunk with halo (zeros outside image)
        for (int i = t; i < CI_T * (H_T + 2) * (WW + 2); i += NTHR) {
            int ci  = i / ((H_T + 2) * (WW + 2));
            int rem = i % ((H_T + 2) * (WW + 2));
            int r   = rem / (WW + 2);
            int c   = rem % (WW + 2);
            int gh  = h0 - 1 + r;
            int gw  = c - 1;
            float v = 0.0f;
            if (gh >= 0 && gh < HH && gw >= 0 && gw < WW)
                v = xbase[((cc * CI_T + ci) * HH + gh) * WW + gw];
            xs[ci][r][c] = v;
        }
        // Stage w chunk
        for (int i = t; i < CO_T * CI_T * 9; i += NTHR) {
            int co  = i / (CI_T * 9);
            int rem = i % (CI_T * 9);
            int ci  = rem / 9;
            int k   = rem % 9;
            ws[co][rem] = g_wq[(size_t)(co0 + co) * CI * 9 + (cc * CI_T + ci) * 9 + k];
        }
        __syncthreads();

        #pragma unroll 2
        for (int ci = 0; ci < CI_T; ci++) {
            #pragma unroll
            for (int kh = 0; kh < 3; kh++) {
                #pragma unroll
                for (int kw = 0; kw < 3; kw++) {
                    float xv[8];
                    #pragma unroll
                    for (int j = 0; j < 8; j++)
                        xv[j] = xs[ci][ph + kh][pw + kw + j];
                    #pragma unroll
                    for (int c = 0; c < 8; c++) {
                        float wv = ws[co_g * 8 + c][ci * 9 + kh * 3 + kw];
                        #pragma unroll
                        for (int j = 0; j < 8; j++)
                            acc[c][j] = fmaf(wv, xv[j], acc[c][j]);
                    }
                }
            }
        }
        __syncthreads();
    }

    // Write output tile
    float* obase = out + ((size_t)n * CO + co0 + co_g * 8) * HH * WW
                       + (h0 + ph) * WW + pw;
    #pragma unroll
    for (int c = 0; c < 8; c++) {
        #pragma unroll
        for (int j = 0; j < 8; j++)
            obase[(size_t)c * HH * WW + j] = acc[c][j];
    }
}

// ---------------------------------------------------------------------------
extern "C" void kernel_launch(void* const* d_in, const int* in_sizes, int n_in,
                              void* d_out, int out_size) {
    // Robust input selection: x has 25,690,112 elements, w has 147,456.
    const float* x = (const float*)d_in[0];
    const float* w = (const float*)d_in[1];
    if (in_sizes[0] == WN && in_sizes[1] == XN) {
        x = (const float*)d_in[1];
        w = (const float*)d_in[0];
    }
    float* out = (float*)d_out;

    quant_x_kernel<<<(XGROUPS + 255) / 256, 256>>>(x);
    quant_w_kernel<<<(WGROUPS + 255) / 256, 256>>>(w);

    dim3 grid(HH / H_T, CO / CO_T, NB);   // (14, 2, 64)
    conv_kernel<<<grid, NTHR>>>(out);
}

// round 4
// speedup vs baseline: 4.6790x; 4.6790x over previous
#include <cuda_runtime.h>
#include <cuda_bf16.h>
#include <cstdint>

// Arch-feature gate: tcgen05 is only legal on sm_103a/sm_100a-specific targets.
#if defined(__CUDA_ARCH_FEAT_SM103_ALL) || defined(__CUDA_ARCH_FEAT_SM100_ALL) || \
    (defined(__CUDA_ARCH_SPECIFIC__) && (__CUDA_ARCH_SPECIFIC__ >= 1000))
#define HAS_TCGEN5 1
#else
#define HAS_TCGEN5 0
#endif

// ---------------- problem constants ----------------
#define NB   64
#define CIN  128
#define COUT 128
#define HH   56
#define WW   56
#define XN   (NB*CIN*HH*WW)        // 25,690,112
#define WN   (COUT*CIN*9)          // 147,456
#define XGROUPS (XN/16)
#define WGROUPS (WN/16)

#define HPAD 58                    // 56 + 2 halo rows
#define XC_PER_N (HPAD*WW*CIN)     // padded pixel rows * ci
#define XC_COPY  (NB*XC_PER_N)

// ---------------- device scratch (no allocs) ----------------
__device__ int g_use_tc;                    // 1 iff tcgen05 SASS path active
__device__ __nv_bfloat16 g_xc[3*XC_COPY];   // 3 kw-shifted NHWC-padded copies
__device__ __nv_bfloat16 g_xqb[XN];         // quantized x, bf16, NCHW
__device__ __nv_bfloat16 g_wq9[9*COUT*CIN]; // quantized w: [k][co][ci]
__device__ float g_xq[XN];                  // quantized x, fp32 (fallback)
__device__ float g_wq[WN];                  // quantized w, fp32 (fallback)

// ---------------- probe: which compilation is running? ----------------
__global__ void probe_tc() {
#if HAS_TCGEN5
    g_use_tc = 1;
#else
    g_use_tc = 0;
#endif
}

// ---------------- BFP quantization (exact, bf16-representable) ----------------
__device__ __forceinline__ void quant16(const float4* p, float* ov) {
    float v[16];
    float4 a = p[0], b = p[1], c = p[2], d = p[3];
    v[0]=a.x;v[1]=a.y;v[2]=a.z;v[3]=a.w; v[4]=b.x;v[5]=b.y;v[6]=b.z;v[7]=b.w;
    v[8]=c.x;v[9]=c.y;v[10]=c.z;v[11]=c.w; v[12]=d.x;v[13]=d.y;v[14]=d.z;v[15]=d.w;
    float m = 0.0f;
    #pragma unroll
    for (int i = 0; i < 16; i++) m = fmaxf(m, fabsf(v[i]));
    if (m > 0.0f) {
        int e = ((__float_as_int(m) >> 23) & 0xFF) - 127;
        float inv_s = ldexpf(1.0f, 7 - e);
        float s     = ldexpf(1.0f, e - 7);
        #pragma unroll
        for (int i = 0; i < 16; i++) {
            float q = rintf(v[i] * inv_s);
            q = fminf(127.0f, fmaxf(-127.0f, q));
            ov[i] = q * s;        // exact: <=8-bit significand, pow2 scale
        }
    } else {
        #pragma unroll
        for (int i = 0; i < 16; i++) ov[i] = 0.0f;
    }
}

__global__ void quant_x16(const float* __restrict__ in) {
    int g = blockIdx.x * blockDim.x + threadIdx.x;
    if (g >= XGROUPS) return;
    float ov[16];
    quant16(reinterpret_cast<const float4*>(in) + (size_t)g * 4, ov);
    // fp32 copy (fallback path)
    float4* pf = reinterpret_cast<float4*>(g_xq) + (size_t)g * 4;
    pf[0] = make_float4(ov[0],ov[1],ov[2],ov[3]);
    pf[1] = make_float4(ov[4],ov[5],ov[6],ov[7]);
    pf[2] = make_float4(ov[8],ov[9],ov[10],ov[11]);
    pf[3] = make_float4(ov[12],ov[13],ov[14],ov[15]);
    // bf16 copy (tensor path) — exact conversion
    __align__(16) __nv_bfloat16 ob[16];
    #pragma unroll
    for (int i = 0; i < 16; i++) ob[i] = __float2bfloat16(ov[i]);
    uint4* dst = reinterpret_cast<uint4*>(g_xqb + (size_t)g * 16);
    dst[0] = *reinterpret_cast<uint4*>(ob);
    dst[1] = *reinterpret_cast<uint4*>(ob + 8);
}

__global__ void quant_w9(const float* __restrict__ in) {
    int g = blockIdx.x * blockDim.x + threadIdx.x;
    if (g >= WGROUPS) return;
    float ov[16];
    quant16(reinterpret_cast<const float4*>(in) + (size_t)g * 4, ov);
    #pragma unroll
    for (int i = 0; i < 16; i++) {
        int flat = g * 16 + i;
        g_wq[flat] = ov[i];
        int k  = flat % 9;
        int t2 = flat / 9;
        int ci = t2 % CIN;
        int co = t2 / CIN;
        g_wq9[(k * COUT + co) * CIN + ci] = __float2bfloat16(ov[i]);
    }
}

// ---------------- build 3 kw-shifted NHWC-padded copies (tensor path) --------
__global__ void build_copies() {
    if (!g_use_tc) return;
    const int hp = blockIdx.x, n = blockIdx.y, kw = blockIdx.z;
    const int t = threadIdx.x;
    __nv_bfloat16* dst = g_xc + (size_t)kw * XC_COPY + ((size_t)n * HPAD + hp) * (WW * CIN);

    if (hp == 0 || hp == HPAD - 1) {
        uint4 z = make_uint4(0, 0, 0, 0);
        for (int i = t; i < WW * CIN / 8; i += 256)
            reinterpret_cast<uint4*>(dst)[i] = z;
        return;
    }
    __shared__ __nv_bfloat16 s[WW][136];
    const int h = hp - 1;
    for (int i = t; i < CIN * 7; i += 256) {
        int ci = i / 7, wc = i % 7;
        uint4 val = *reinterpret_cast<const uint4*>(
            g_xqb + ((size_t)(n * CIN + ci) * (HH * WW) + h * WW + wc * 8));
        __nv_bfloat16 tmp[8];
        *reinterpret_cast<uint4*>(tmp) = val;
        #pragma unroll
        for (int j = 0; j < 8; j++) s[wc * 8 + j][ci] = tmp[j];
    }
    __syncthreads();
    for (int i = t; i < WW * 16; i += 256) {
        int w = i / 16, c = i % 16;
        int wsrc = w + kw - 1;
        uint4 v = make_uint4(0, 0, 0, 0);
        if (wsrc >= 0 && wsrc < WW)
            v = *reinterpret_cast<uint4*>(&s[wsrc][c * 8]);
        *reinterpret_cast<uint4*>(dst + (w * CIN + c * 8)) = v;
    }
}

// ---------------- tcgen05 helpers (guarded) ----------------
#if HAS_TCGEN5
__device__ __forceinline__ uint32_t elect_one_pred() {
    uint32_t pred;
    asm volatile("{\n\t.reg .pred p;\n\telect.sync _|p, 0xFFFFFFFF;\n\t"
                 "selp.b32 %0, 1, 0, p;\n\t}" : "=r"(pred));
    return pred;
}
#define TC_ALLOC(sm, n)  asm volatile("tcgen05.alloc.cta_group::1.sync.aligned.shared::cta.b32 [%0], %1;" :: "r"(sm), "r"((uint32_t)(n)) : "memory")
#define TC_DEALLOC(t, n) asm volatile("tcgen05.dealloc.cta_group::1.sync.aligned.b32 %0, %1;" :: "r"(t), "r"((uint32_t)(n)))
#define TC_RELINQ()      asm volatile("tcgen05.relinquish_alloc_permit.cta_group::1.sync.aligned;")
#define TC_COMMIT(mb)    asm volatile("tcgen05.commit.cta_group::1.mbarrier::arrive::one.shared::cluster.b64 [%0];" :: "r"(mb) : "memory")
#define TC_FENCE_AFTER() asm volatile("tcgen05.fence::after_thread_sync;" ::: "memory")
#define TC_WAIT_LD()     asm volatile("tcgen05.wait::ld.sync.aligned;" ::: "memory")
#define FENCE_ASYNC()    asm volatile("fence.proxy.async.shared::cta;" ::: "memory")
#define MBAR_INIT(mb, c) asm volatile("mbarrier.init.shared.b64 [%0], %1;" :: "r"(mb), "r"((uint32_t)(c)) : "memory")

__device__ __forceinline__ void mbar_wait(uint32_t mb, uint32_t parity) {
    asm volatile(
        "{\n\t.reg .pred P1;\n\t"
        "WL_%=:\n\t"
        "mbarrier.try_wait.parity.acquire.cta.shared::cta.b64 P1, [%0], %1, 0x989680;\n\t"
        "@P1 bra.uni WD_%=;\n\t"
        "bra.uni WL_%=;\n\t"
        "WD_%=:\n\t}"
        :: "r"(mb), "r"(parity) : "memory");
}

#define TC_LD_X32(r, ta) \
    asm volatile("tcgen05.ld.sync.aligned.32x32b.x32.b32 " \
        "{%0,%1,%2,%3,%4,%5,%6,%7,%8,%9,%10,%11,%12,%13,%14,%15," \
        "%16,%17,%18,%19,%20,%21,%22,%23,%24,%25,%26,%27,%28,%29,%30,%31}, [%32];" \
        : "=r"((r)[0]),"=r"((r)[1]),"=r"((r)[2]),"=r"((r)[3]),"=r"((r)[4]),"=r"((r)[5]),"=r"((r)[6]),"=r"((r)[7]), \
          "=r"((r)[8]),"=r"((r)[9]),"=r"((r)[10]),"=r"((r)[11]),"=r"((r)[12]),"=r"((r)[13]),"=r"((r)[14]),"=r"((r)[15]), \
          "=r"((r)[16]),"=r"((r)[17]),"=r"((r)[18]),"=r"((r)[19]),"=r"((r)[20]),"=r"((r)[21]),"=r"((r)[22]),"=r"((r)[23]), \
          "=r"((r)[24]),"=r"((r)[25]),"=r"((r)[26]),"=r"((r)[27]),"=r"((r)[28]),"=r"((r)[29]),"=r"((r)[30]),"=r"((r)[31]) \
        : "r"(ta))

__device__ __forceinline__ void mma_f16_ss(uint32_t d, uint64_t a, uint64_t b,
                                           uint32_t idesc, uint32_t en) {
    asm volatile(
        "{\n\t.reg .pred p;\n\tsetp.ne.u32 p, %4, 0;\n\t"
        "tcgen05.mma.cta_group::1.kind::f16 [%0], %1, %2, %3, {%5,%5,%5,%5}, p;\n\t}"
        :: "r"(d), "l"(a), "l"(b), "r"(idesc), "r"(en), "r"(0u) : "memory");
}
#endif // HAS_TCGEN5

__device__ __forceinline__ uint32_t smem_u32(const void* p) {
    uint32_t a;
    asm("{ .reg .u64 t; cvta.to.shared.u64 t, %1; cvt.u32.u64 %0, t; }" : "=r"(a) : "l"(p));
    return a;
}

// SW128 K-major descriptor base (LBO=1, SBO=64, version=1, layout=SW128)
#define DESC_BASE ((2ULL<<61) | (1ULL<<46) | (64ULL<<32) | (1ULL<<16))
__device__ __forceinline__ uint64_t mk_desc(uint32_t a) {
    return DESC_BASE | (uint64_t)((a >> 4) & 0x3FFF);
}
// idesc: F32 acc, BF16 a/b, N=224, M=128
#define IDESC (0x10u | 0x80u | 0x400u | (28u<<17) | (8u<<24))

// ---------------- tcgen05 conv kernel ----------------
#define SM_TPTR 0
#define SM_MBAR 8
#define SM_A0   1024
#define SM_A1   (1024 + 32768)
#define SM_B    (1024 + 65536)
#define B_ROWS  336
#define NAR_A   16
#define NAR_B   42
#define CONV_SMEM (SM_B + B_ROWS*256)   // 152,576

template <int ROWS, int NAR>
__device__ __forceinline__ void stage_tile(char* smem, uint32_t sm_off,
                                           const char* __restrict__ gsrc) {
    #pragma unroll 4
    for (int i = threadIdx.x; i < ROWS * 16; i += 128) {
        int lr = i >> 4, c = i & 15;
        uint4 v = *reinterpret_cast<const uint4*>(gsrc + ((size_t)lr << 8) + (c << 4));
        uint32_t byte = (uint32_t)((lr >> 3) + (c >> 3) * NAR) * 1024u
                      + (uint32_t)(lr & 7) * 128u + (uint32_t)(c & 7) * 16u;
        byte ^= (byte >> 3) & 0x70u;
        *reinterpret_cast<uint4*>(smem + sm_off + byte) = v;
    }
}

__global__ __launch_bounds__(128, 1)
void conv_mma_kernel(float* __restrict__ out) {
#if HAS_TCGEN5
    extern __shared__ char smem[];
    const int rg = blockIdx.x;       // 0..13 (4 output rows each)
    const int n  = blockIdx.y;       // 0..63
    const int tid = threadIdx.x;
    const int wid = tid >> 5, lane = tid & 31;
    const uint32_t sb = smem_u32(smem);

    if (wid == 0) TC_ALLOC(sb + SM_TPTR, 256);
    if (tid == 0) {
        #pragma unroll
        for (int s = 0; s < 9; s++) MBAR_INIT(sb + SM_MBAR + s * 8, 1);
    }
    __syncthreads();
    uint32_t tmem;
    asm volatile("ld.shared.b32 %0, [%1];" : "=r"(tmem) : "r"(sb + SM_TPTR));
    if (wid == 0) TC_RELINQ();

    const uint64_t adesc[2] = { mk_desc(sb + SM_A0), mk_desc(sb + SM_A1) };
    const uint64_t bdesc = mk_desc(sb + SM_B);
    const size_t rowbase = (size_t)n * (HPAD * WW) + (size_t)rg * 224;

    #pragma unroll
    for (int s = 0; s < 9; s++) {
        const int kw = s / 3, kh = s % 3;
        if (kh == 0) {
            if (s > 0) mbar_wait(sb + SM_MBAR + (s - 1) * 8, 0);  // drain before B overwrite
            stage_tile<B_ROWS, NAR_B>(smem, SM_B,
                (const char*)(g_xc + (size_t)kw * XC_COPY + rowbase * CIN));
        } else if (s >= 2) {
            mbar_wait(sb + SM_MBAR + (s - 2) * 8, 0);             // frees A buf s&1
        }
        stage_tile<128, NAR_A>(smem, (s & 1) ? SM_A1 : SM_A0,
            (const char*)(g_wq9 + (size_t)(kh * 3 + kw) * COUT * CIN));
        FENCE_ASYNC();
        __syncthreads();
        if (tid < 32 && elect_one_pred()) {
            const uint64_t ad = adesc[s & 1];
            const uint64_t bd = bdesc + (uint64_t)(kh * 448);
            #pragma unroll
            for (int k = 0; k < 8; k++) {
                mma_f16_ss(tmem,
                           ad + (uint64_t)((k & 3) * 2 + (k >> 2) * 1024),
                           bd + (uint64_t)((k & 3) * 2 + (k >> 2) * 2688),
                           IDESC, (s > 0 || k > 0) ? 1u : 0u);
            }
            TC_COMMIT(sb + SM_MBAR + s * 8);
        }
    }

    mbar_wait(sb + SM_MBAR + 8 * 8, 0);
    TC_FENCE_AFTER();

    float* obase = out + ((size_t)n * COUT + (wid * 32 + lane)) * (HH * WW)
                       + (size_t)rg * 224;
    #pragma unroll
    for (int ch = 0; ch < 7; ch++) {
        uint32_t v[32];
        TC_LD_X32(v, tmem + ch * 32);
        TC_WAIT_LD();
        #pragma unroll
        for (int j = 0; j < 32; j += 4)
            *reinterpret_cast<float4*>(obase + ch * 32 + j) =
                make_float4(__uint_as_float(v[j]),     __uint_as_float(v[j + 1]),
                            __uint_as_float(v[j + 2]), __uint_as_float(v[j + 3]));
    }
    __syncthreads();
    if (wid == 0) TC_DEALLOC(tmem, 256);
#endif // HAS_TCGEN5
}

// ---------------- fp32 fallback conv (proven R2 path) ----------------
#define CI_T 8
#define CO_T 64
#define H_T  4
#define NTHR 224

__global__ __launch_bounds__(NTHR, 2)
void conv_fallback(float* __restrict__ out) {
    if (g_use_tc) return;   // tensor path owns the output
    __shared__ float xs[CI_T][H_T + 2][WW + 2];
    __shared__ float ws[CO_T][CI_T * 9];

    const int t   = threadIdx.x;
    const int hb  = blockIdx.x;
    const int cb  = blockIdx.y;
    const int n   = blockIdx.z;
    const int h0  = hb * H_T;
    const int co0 = cb * CO_T;

    const int co_g = t / 28;
    const int pix  = t % 28;
    const int ph   = pix / 7;
    const int pw   = (pix % 7) * 8;

    float acc[8][8];
    #pragma unroll
    for (int c = 0; c < 8; c++)
        #pragma unroll
        for (int j = 0; j < 8; j++) acc[c][j] = 0.0f;

    const float* xbase = g_xq + (size_t)n * CIN * HH * WW;

    for (int cc = 0; cc < CIN / CI_T; cc++) {
        for (int i = t; i < CI_T * (H_T + 2) * (WW + 2); i += NTHR) {
            int ci  = i / ((H_T + 2) * (WW + 2));
            int rem = i % ((H_T + 2) * (WW + 2));
            int r   = rem / (WW + 2);
            int c   = rem % (WW + 2);
            int gh  = h0 - 1 + r;
            int gw  = c - 1;
            float v = 0.0f;
            if (gh >= 0 && gh < HH && gw >= 0 && gw < WW)
                v = xbase[((cc * CI_T + ci) * HH + gh) * WW + gw];
            xs[ci][r][c] = v;
        }
        for (int i = t; i < CO_T * CI_T * 9; i += NTHR) {
            int co  = i / (CI_T * 9);
            int rem = i % (CI_T * 9);
            ws[co][rem] = g_wq[(size_t)(co0 + co) * CIN * 9 + (cc * CI_T) * 9 + rem];
        }
        __syncthreads();

        #pragma unroll 2
        for (int ci = 0; ci < CI_T; ci++) {
            #pragma unroll
            for (int kh = 0; kh < 3; kh++) {
                #pragma unroll
                for (int kw = 0; kw < 3; kw++) {
                    float xv[8];
                    #pragma unroll
                    for (int j = 0; j < 8; j++)
                        xv[j] = xs[ci][ph + kh][pw + kw + j];
                    #pragma unroll
                    for (int c = 0; c < 8; c++) {
                        float wv = ws[co_g * 8 + c][ci * 9 + kh * 3 + kw];
                        #pragma unroll
                        for (int j = 0; j < 8; j++)
                            acc[c][j] = fmaf(wv, xv[j], acc[c][j]);
                    }
                }
            }
        }
        __syncthreads();
    }

    float* obase = out + ((size_t)n * COUT + co0 + co_g * 8) * HH * WW
                       + (h0 + ph) * WW + pw;
    #pragma unroll
    for (int c = 0; c < 8; c++) {
        #pragma unroll
        for (int j = 0; j < 8; j++)
            obase[(size_t)c * HH * WW + j] = acc[c][j];
    }
}

// ---------------- launch ----------------
extern "C" void kernel_launch(void* const* d_in, const int* in_sizes, int n_in,
                              void* d_out, int out_size) {
    const float* x = (const float*)d_in[0];
    const float* w = (const float*)d_in[1];
    if (in_sizes[0] == WN && in_sizes[1] == XN) {
        x = (const float*)d_in[1];
        w = (const float*)d_in[0];
    }
    float* out = (float*)d_out;

    cudaFuncSetAttribute(conv_mma_kernel,
                         cudaFuncAttributeMaxDynamicSharedMemorySize, CONV_SMEM);

    probe_tc<<<1, 1>>>();
    quant_x16<<<(XGROUPS + 255) / 256, 256>>>(x);
    quant_w9<<<(WGROUPS + 255) / 256, 256>>>(w);
    build_copies<<<dim3(HPAD, NB, 3), 256>>>();
    conv_mma_kernel<<<dim3(14, NB), 128, CONV_SMEM>>>(out);
    conv_fallback<<<dim3(HH / H_T, COUT / CO_T, NB), NTHR>>>(out);
}

// round 5
// speedup vs baseline: 11.3219x; 2.4197x over previous
#include <cuda_runtime.h>
#include <cuda_bf16.h>
#include <cstdint>

// Arch-feature gate: tcgen05 only legal on sm_103a/sm_100a-specific targets.
#if defined(__CUDA_ARCH_FEAT_SM103_ALL) || defined(__CUDA_ARCH_FEAT_SM100_ALL) || \
    (defined(__CUDA_ARCH_SPECIFIC__) && (__CUDA_ARCH_SPECIFIC__ >= 1000))
#define HAS_TCGEN5 1
#else
#define HAS_TCGEN5 0
#endif

// ---------------- problem constants ----------------
#define NB   64
#define CIN  128
#define COUT 128
#define HH   56
#define WW   56
#define XN   (NB*CIN*HH*WW)
#define WN   (COUT*CIN*9)
#define WGROUPS (WN/16)

#define HPAD 58
#define XC_PER_N (HPAD*WW*CIN)
#define XC_COPY  ((size_t)NB*XC_PER_N)

// ---------------- device scratch ----------------
__device__ __nv_bfloat16 g_xc[3*NB*HPAD*WW*CIN]; // 3 kw-shifted padded copies
__device__ __nv_bfloat16 g_wq9[9*COUT*CIN];      // quantized w: [k][co][ci]

// ---------------- BFP quantization (exact, bf16-representable) ----------------
__device__ __forceinline__ void quant16(const float4* p, float* ov) {
    float v[16];
    float4 a = p[0], b = p[1], c = p[2], d = p[3];
    v[0]=a.x;v[1]=a.y;v[2]=a.z;v[3]=a.w; v[4]=b.x;v[5]=b.y;v[6]=b.z;v[7]=b.w;
    v[8]=c.x;v[9]=c.y;v[10]=c.z;v[11]=c.w; v[12]=d.x;v[13]=d.y;v[14]=d.z;v[15]=d.w;
    float m = 0.0f;
    #pragma unroll
    for (int i = 0; i < 16; i++) m = fmaxf(m, fabsf(v[i]));
    if (m > 0.0f) {
        int e = ((__float_as_int(m) >> 23) & 0xFF) - 127;
        float inv_s = ldexpf(1.0f, 7 - e);
        float s     = ldexpf(1.0f, e - 7);
        #pragma unroll
        for (int i = 0; i < 16; i++) {
            float q = rintf(v[i] * inv_s);
            q = fminf(127.0f, fmaxf(-127.0f, q));
            ov[i] = q * s;
        }
    } else {
        #pragma unroll
        for (int i = 0; i < 16; i++) ov[i] = 0.0f;
    }
}

// ---------------- fused quant + transpose + 3x kw-shift for x ----------------
// Block: (h_chunk, ci_chunk, n) = 8 h-rows x 16 ci. Groups of 16 flat elements
// are fully contained (8*56 = 448 = 28 groups per ci, chunk-aligned).
__global__ __launch_bounds__(256)
void quant_transpose_x(const float* __restrict__ in) {
    __shared__ uint32_t sq[16][229];   // [ci][pixel-pair], padded vs bank conflicts
    const int hc = blockIdx.x;   // 0..6
    const int cc = blockIdx.y;   // 0..7
    const int n  = blockIdx.z;   // 0..63
    const int tid = threadIdx.x;
    const int h0 = hc * 8, ci0 = cc * 16;

    // Phase 1: quantize 448 groups (16 ci x 28 groups), store bf16x2 to smem
    for (int g2 = tid; g2 < 448; g2 += 256) {
        int ci = g2 / 28, grp = g2 % 28;
        const float4* src = reinterpret_cast<const float4*>(
            in + ((size_t)(n * CIN + ci0 + ci) * (HH * WW) + h0 * WW + grp * 16));
        float ov[16];
        quant16(src, ov);
        int wbase = grp * 8;
        #pragma unroll
        for (int j = 0; j < 8; j++) {
            uint32_t lo = __bfloat16_as_ushort(__float2bfloat16(ov[2*j]));
            uint32_t hi = __bfloat16_as_ushort(__float2bfloat16(ov[2*j+1]));
            sq[ci][wbase + j] = (hi << 16) | lo;
        }
    }
    __syncthreads();

    // Phase 2: write [kw][n][hp][w][ci] (pixel rows of 128 ci, 16 ci per block)
    for (int i = tid; i < 896; i += 256) {
        int pos = i >> 1, half = i & 1;
        int r = pos / WW, w = pos % WW;
        size_t rowbase = ((size_t)n * HPAD + h0 + r + 1) * WW;
        #pragma unroll
        for (int kw = 0; kw < 3; kw++) {
            int wsrc = w + kw - 1;
            uint4 v = make_uint4(0, 0, 0, 0);
            if (wsrc >= 0 && wsrc < WW) {
                int pix = r * WW + wsrc;
                int word = pix >> 1, sh = (pix & 1) * 16;
                uint32_t e0 = (sq[half*8+0][word] >> sh) & 0xFFFF;
                uint32_t e1 = (sq[half*8+1][word] >> sh) & 0xFFFF;
                uint32_t e2 = (sq[half*8+2][word] >> sh) & 0xFFFF;
                uint32_t e3 = (sq[half*8+3][word] >> sh) & 0xFFFF;
                uint32_t e4 = (sq[half*8+4][word] >> sh) & 0xFFFF;
                uint32_t e5 = (sq[half*8+5][word] >> sh) & 0xFFFF;
                uint32_t e6 = (sq[half*8+6][word] >> sh) & 0xFFFF;
                uint32_t e7 = (sq[half*8+7][word] >> sh) & 0xFFFF;
                v.x = e0 | (e1 << 16); v.y = e2 | (e3 << 16);
                v.z = e4 | (e5 << 16); v.w = e6 | (e7 << 16);
            }
            *reinterpret_cast<uint4*>(g_xc + kw * XC_COPY
                + (rowbase + w) * CIN + ci0 + half * 8) = v;
        }
    }

    // Halo rows (hp = 0 and 57): zeroed by ci_chunk 0 blocks
    if (cc == 0 && (hc == 0 || hc == 6)) {
        int hp = (hc == 0) ? 0 : (HPAD - 1);
        size_t base = ((size_t)n * HPAD + hp) * WW * CIN;
        uint4 z = make_uint4(0, 0, 0, 0);
        #pragma unroll
        for (int kw = 0; kw < 3; kw++)
            for (int i = tid; i < WW * CIN / 8; i += 256)
                reinterpret_cast<uint4*>(g_xc + kw * XC_COPY + base)[i] = z;
    }
}

__global__ void quant_w9(const float* __restrict__ in) {
    int g = blockIdx.x * blockDim.x + threadIdx.x;
    if (g >= WGROUPS) return;
    float ov[16];
    quant16(reinterpret_cast<const float4*>(in) + (size_t)g * 4, ov);
    #pragma unroll
    for (int i = 0; i < 16; i++) {
        int flat = g * 16 + i;
        int k  = flat % 9;
        int t2 = flat / 9;
        int ci = t2 % CIN;
        int co = t2 / CIN;
        g_wq9[(k * COUT + co) * CIN + ci] = __float2bfloat16(ov[i]);
    }
}

// ---------------- tcgen05 helpers ----------------
#if HAS_TCGEN5
__device__ __forceinline__ uint32_t elect_one_pred() {
    uint32_t pred;
    asm volatile("{\n\t.reg .pred p;\n\telect.sync _|p, 0xFFFFFFFF;\n\t"
                 "selp.b32 %0, 1, 0, p;\n\t}" : "=r"(pred));
    return pred;
}
#define TC_ALLOC(sm, n)  asm volatile("tcgen05.alloc.cta_group::1.sync.aligned.shared::cta.b32 [%0], %1;" :: "r"(sm), "r"((uint32_t)(n)) : "memory")
#define TC_DEALLOC(t, n) asm volatile("tcgen05.dealloc.cta_group::1.sync.aligned.b32 %0, %1;" :: "r"(t), "r"((uint32_t)(n)))
#define TC_RELINQ()      asm volatile("tcgen05.relinquish_alloc_permit.cta_group::1.sync.aligned;")
#define TC_COMMIT(mb)    asm volatile("tcgen05.commit.cta_group::1.mbarrier::arrive::one.shared::cluster.b64 [%0];" :: "r"(mb) : "memory")
#define TC_FENCE_AFTER() asm volatile("tcgen05.fence::after_thread_sync;" ::: "memory")
#define TC_WAIT_LD()     asm volatile("tcgen05.wait::ld.sync.aligned;" ::: "memory")
#define FENCE_ASYNC()    asm volatile("fence.proxy.async.shared::cta;" ::: "memory")
#define MBAR_INIT(mb, c) asm volatile("mbarrier.init.shared.b64 [%0], %1;" :: "r"(mb), "r"((uint32_t)(c)) : "memory")
#define CP_COMMIT()      asm volatile("cp.async.commit_group;" ::: "memory")
#define CP_WAIT0()       asm volatile("cp.async.wait_group 0;" ::: "memory")

__device__ __forceinline__ void cp16(uint32_t dst, const void* src) {
    asm volatile("cp.async.cg.shared.global [%0], [%1], 16;"
                 :: "r"(dst), "l"(src) : "memory");
}

__device__ __forceinline__ void mbar_wait(uint32_t mb, uint32_t parity) {
    asm volatile(
        "{\n\t.reg .pred P1;\n\t"
        "WL_%=:\n\t"
        "mbarrier.try_wait.parity.acquire.cta.shared::cta.b64 P1, [%0], %1, 0x989680;\n\t"
        "@P1 bra.uni WD_%=;\n\t"
        "bra.uni WL_%=;\n\t"
        "WD_%=:\n\t}"
        :: "r"(mb), "r"(parity) : "memory");
}

#define TC_LD_X32(r, ta) \
    asm volatile("tcgen05.ld.sync.aligned.32x32b.x32.b32 " \
        "{%0,%1,%2,%3,%4,%5,%6,%7,%8,%9,%10,%11,%12,%13,%14,%15," \
        "%16,%17,%18,%19,%20,%21,%22,%23,%24,%25,%26,%27,%28,%29,%30,%31}, [%32];" \
        : "=r"((r)[0]),"=r"((r)[1]),"=r"((r)[2]),"=r"((r)[3]),"=r"((r)[4]),"=r"((r)[5]),"=r"((r)[6]),"=r"((r)[7]), \
          "=r"((r)[8]),"=r"((r)[9]),"=r"((r)[10]),"=r"((r)[11]),"=r"((r)[12]),"=r"((r)[13]),"=r"((r)[14]),"=r"((r)[15]), \
          "=r"((r)[16]),"=r"((r)[17]),"=r"((r)[18]),"=r"((r)[19]),"=r"((r)[20]),"=r"((r)[21]),"=r"((r)[22]),"=r"((r)[23]), \
          "=r"((r)[24]),"=r"((r)[25]),"=r"((r)[26]),"=r"((r)[27]),"=r"((r)[28]),"=r"((r)[29]),"=r"((r)[30]),"=r"((r)[31]) \
        : "r"(ta))

#define TC_LD_X16(r, ta) \
    asm volatile("tcgen05.ld.sync.aligned.32x32b.x16.b32 " \
        "{%0,%1,%2,%3,%4,%5,%6,%7,%8,%9,%10,%11,%12,%13,%14,%15}, [%16];" \
        : "=r"((r)[0]),"=r"((r)[1]),"=r"((r)[2]),"=r"((r)[3]),"=r"((r)[4]),"=r"((r)[5]),"=r"((r)[6]),"=r"((r)[7]), \
          "=r"((r)[8]),"=r"((r)[9]),"=r"((r)[10]),"=r"((r)[11]),"=r"((r)[12]),"=r"((r)[13]),"=r"((r)[14]),"=r"((r)[15]) \
        : "r"(ta))

__device__ __forceinline__ void mma_f16_ss(uint32_t d, uint64_t a, uint64_t b,
                                           uint32_t idesc, uint32_t en) {
    asm volatile(
        "{\n\t.reg .pred p;\n\tsetp.ne.u32 p, %4, 0;\n\t"
        "tcgen05.mma.cta_group::1.kind::f16 [%0], %1, %2, %3, {%5,%5,%5,%5}, p;\n\t}"
        :: "r"(d), "l"(a), "l"(b), "r"(idesc), "r"(en), "r"(0u) : "memory");
}
#endif // HAS_TCGEN5

__device__ __forceinline__ uint32_t smem_u32(const void* p) {
    uint32_t a;
    asm("{ .reg .u64 t; cvta.to.shared.u64 t, %1; cvt.u32.u64 %0, t; }" : "=r"(a) : "l"(p));
    return a;
}

#define DESC_BASE ((2ULL<<61) | (1ULL<<46) | (64ULL<<32) | (1ULL<<16))
__device__ __forceinline__ uint64_t mk_desc(uint32_t a) {
    return DESC_BASE | (uint64_t)((a >> 4) & 0x3FFF);
}
// idesc: F32 acc, BF16 a/b, N=112, M=128
#define IDESC (0x10u | 0x80u | 0x400u | (14u<<17) | (8u<<24))

// ---------------- tcgen05 conv kernel ----------------
// CTA = image n, 8 output rows (4 D-tiles of N=112). B = 560 pixel rows (143KB)
// staged once per kw (3x); A = w[kh*3+kw] 32KB, double-buffered, per stage.
// 9 stages x 4 tiles x 8 K-steps. D tiles in TMEM cols t*112.
#define SM_TPTR 0
#define SM_MBAR 8
#define SM_A0   1024
#define SM_A1   (1024 + 32768)
#define SM_B    (1024 + 65536)
#define B_ROWS  560
#define NAR_A   16
#define NAR_B   70
#define CONV_SMEM (SM_B + B_ROWS*256)   // 209,920

__global__ __launch_bounds__(128, 1)
void conv_mma_kernel(float* __restrict__ out) {
#if HAS_TCGEN5
    extern __shared__ char smem[];
    const int rgi = blockIdx.x;      // 0..6  (8 output rows each)
    const int n   = blockIdx.y;      // 0..63
    const int tid = threadIdx.x;
    const int wid = tid >> 5, lane = tid & 31;
    const uint32_t sb = smem_u32(smem);
    const int h0 = rgi * 8;

    if (wid == 0) TC_ALLOC(sb + SM_TPTR, 512);
    if (tid == 0) {
        #pragma unroll
        for (int s = 0; s < 9; s++) MBAR_INIT(sb + SM_MBAR + s * 8, 1);
    }
    __syncthreads();
    uint32_t tmem;
    asm volatile("ld.shared.b32 %0, [%1];" : "=r"(tmem) : "r"(sb + SM_TPTR));
    if (wid == 0) TC_RELINQ();

    const uint64_t adesc[2] = { mk_desc(sb + SM_A0), mk_desc(sb + SM_A1) };
    const uint64_t bdesc = mk_desc(sb + SM_B);
    const char* bsrc_n = (const char*)(g_xc)
        + (((size_t)n * HPAD + h0) * WW * CIN) * 2;   // bytes

    #pragma unroll
    for (int s = 0; s < 9; s++) {
        const int kw = s / 3, kh = s % 3;
        if (kh == 0) {
            if (s > 0) mbar_wait(sb + SM_MBAR + (s - 1) * 8, 0);
            // stage B: 560 rows x 256B, SW128 blocked atoms, 70 cp per thread
            const char* gB = bsrc_n + (size_t)kw * (XC_COPY * 2);
            #pragma unroll 5
            for (int it = 0; it < 70; it++) {
                int i = tid + it * 128;
                int lr = i >> 4, c = i & 15;
                uint32_t byte = (uint32_t)((lr >> 3) + (c >> 3) * NAR_B) * 1024u
                              + (uint32_t)(lr & 7) * 128u + (uint32_t)(c & 7) * 16u;
                byte ^= (byte >> 3) & 0x70u;
                cp16(sb + SM_B + byte, gB + ((size_t)lr << 8) + (c << 4));
            }
        } else if (s >= 2) {
            mbar_wait(sb + SM_MBAR + (s - 2) * 8, 0);
        }
        // stage A (weights for this (kh,kw)): 128 rows x 256B, 16 cp per thread
        {
            const char* gA = (const char*)(g_wq9 + (size_t)(kh * 3 + kw) * COUT * CIN);
            uint32_t abuf = sb + ((s & 1) ? SM_A1 : SM_A0);
            #pragma unroll
            for (int it = 0; it < 16; it++) {
                int i = tid + it * 128;
                int lr = i >> 4, c = i & 15;
                uint32_t byte = (uint32_t)((lr >> 3) + (c >> 3) * NAR_A) * 1024u
                              + (uint32_t)(lr & 7) * 128u + (uint32_t)(c & 7) * 16u;
                byte ^= (byte >> 3) & 0x70u;
                cp16(abuf + byte, gA + ((size_t)lr << 8) + (c << 4));
            }
        }
        CP_COMMIT();
        CP_WAIT0();
        FENCE_ASYNC();
        __syncthreads();
        if (tid < 32 && elect_one_pred()) {
            const uint64_t ad = adesc[s & 1];
            #pragma unroll
            for (int t = 0; t < 4; t++) {
                const uint64_t bd = bdesc + (uint64_t)((2 * t + kh) * 448);
                #pragma unroll
                for (int k = 0; k < 8; k++) {
                    mma_f16_ss(tmem + t * 112,
                               ad + (uint64_t)((k & 3) * 2 + (k >> 2) * 1024),
                               bd + (uint64_t)((k & 3) * 2 + (k >> 2) * 4480),
                               IDESC, (s > 0 || k > 0) ? 1u : 0u);
                }
            }
            TC_COMMIT(sb + SM_MBAR + s * 8);
        }
    }

    mbar_wait(sb + SM_MBAR + 8 * 8, 0);
    TC_FENCE_AFTER();

    // Epilogue: co = wid*32+lane; tile t -> 112 contiguous floats at h0*56 + t*112
    float* ob = out + ((size_t)n * COUT + (wid * 32 + lane)) * (HH * WW)
                    + (size_t)h0 * WW;
    #pragma unroll
    for (int t = 0; t < 4; t++) {
        uint32_t v[32];
        #pragma unroll
        for (int ch = 0; ch < 3; ch++) {
            TC_LD_X32(v, tmem + t * 112 + ch * 32);
            TC_WAIT_LD();
            #pragma unroll
            for (int j = 0; j < 32; j += 4)
                *reinterpret_cast<float4*>(ob + t * 112 + ch * 32 + j) =
                    make_float4(__uint_as_float(v[j]),     __uint_as_float(v[j+1]),
                                __uint_as_float(v[j+2]),   __uint_as_float(v[j+3]));
        }
        TC_LD_X16(v, tmem + t * 112 + 96);
        TC_WAIT_LD();
        #pragma unroll
        for (int j = 0; j < 16; j += 4)
            *reinterpret_cast<float4*>(ob + t * 112 + 96 + j) =
                make_float4(__uint_as_float(v[j]),   __uint_as_float(v[j+1]),
                            __uint_as_float(v[j+2]), __uint_as_float(v[j+3]));
    }
    __syncthreads();
    if (wid == 0) TC_DEALLOC(tmem, 512);
#endif // HAS_TCGEN5
}

// ---------------- launch ----------------
extern "C" void kernel_launch(void* const* d_in, const int* in_sizes, int n_in,
                              void* d_out, int out_size) {
    const float* x = (const float*)d_in[0];
    const float* w = (const float*)d_in[1];
    if (in_sizes[0] == WN && in_sizes[1] == XN) {
        x = (const float*)d_in[1];
        w = (const float*)d_in[0];
    }
    float* out = (float*)d_out;

    cudaFuncSetAttribute(conv_mma_kernel,
                         cudaFuncAttributeMaxDynamicSharedMemorySize, CONV_SMEM);

    quant_transpose_x<<<dim3(7, 8, NB), 256>>>(x);
    quant_w9<<<(WGROUPS + 255) / 256, 256>>>(w);
    conv_mma_kernel<<<dim3(7, NB), 128, CONV_SMEM>>>(out);
}